// round 15
// baseline (speedup 1.0000x reference)
#include <cuda_runtime.h>
#include <cuda_bf16.h>
#include <cuda_fp16.h>
#include <cstdint>

// Problem constants
#define BB 4
#define TT 2048
#define CC 1024
#define HH 16
#define DD 64
#define MM (BB*TT)        // 8192

#define SCALE_EXP2 0.1803368801111204f   // 0.125 * log2(e)

// Scratch (device globals: allocation-free rule)
__device__ uint32_t g_q16[(size_t)MM * CC / 2];  // fp16 pair-packed prescaled Q
__device__ uint32_t g_k16[(size_t)MM * CC / 2];  // fp16 pair-packed K
__device__ __half   g_v16[(size_t)MM * CC];      // fp16 V, [b,tile,h][d][tk_perm]
__device__ __half   g_att16[(size_t)MM * CC];    // attention out, fp16 perm
__device__ __half   g_x16[(size_t)MM * CC];      // fp16 perm x
__device__ __half   g_wqkvT16[(size_t)3 * CC * CC];
__device__ __half   g_woutT16[(size_t)CC * CC];

// ---------------------------------------------------------------------------
// Helpers
// ---------------------------------------------------------------------------
__device__ __forceinline__ float ex2(float x) {
    float y;
    asm("ex2.approx.ftz.f32 %0, %1;" : "=f"(y) : "f"(x));
    return y;
}

__device__ __forceinline__ uint32_t ex2_f16x2(uint32_t x) {
    uint32_t y;
    asm("ex2.approx.f16x2 %0, %1;" : "=r"(y) : "r"(x));
    return y;
}

__device__ __forceinline__ uint32_t pack_f16x2(float x, float y) {
    uint32_t r;
    asm("cvt.rn.f16x2.f32 %0, %1, %2;" : "=r"(r) : "f"(y), "f"(x));
    return r;
}

// m16n8k16 f16 mma, fp32 accumulate
__device__ __forceinline__ void mma_f16(float* c, const uint32_t* a,
                                        uint32_t b0, uint32_t b1) {
    asm volatile(
        "mma.sync.aligned.m16n8k16.row.col.f32.f16.f16.f32 "
        "{%0,%1,%2,%3}, {%4,%5,%6,%7}, {%8,%9}, {%0,%1,%2,%3};\n"
        : "+f"(c[0]), "+f"(c[1]), "+f"(c[2]), "+f"(c[3])
        : "r"(a[0]), "r"(a[1]), "r"(a[2]), "r"(a[3]),
          "r"(b0), "r"(b1));
}

__device__ __forceinline__ void cp_async16(uint32_t dst, const void* src) {
    asm volatile("cp.async.cg.shared.global [%0], [%1], 16;\n"
                 :: "r"(dst), "l"(src));
}
__device__ __forceinline__ void cp_commit() {
    asm volatile("cp.async.commit_group;\n" ::: "memory");
}
__device__ __forceinline__ void cp_wait1() {
    asm volatile("cp.async.wait_group 1;\n" ::: "memory");
}
__device__ __forceinline__ void cp_wait0() {
    asm volatile("cp.async.wait_group 0;\n" ::: "memory");
}

__device__ __forceinline__ uint32_t smem_u32(const void* p) {
    uint32_t a;
    asm("{ .reg .u64 t; cvta.to.shared.u64 t, %1; cvt.u32.u64 %0, t; }"
        : "=r"(a) : "l"(p));
    return a;
}

__device__ __forceinline__ int pp_slot(int u) {   // pair-pack slot, u in 0..7
    return 2 * (u & 3) + (u >> 2);
}

// ---------------------------------------------------------------------------
// x -> fp16 pair-pack-permuted (GEMM A operand format)
// ---------------------------------------------------------------------------
__global__ void f16perm_convert_kernel(const float* __restrict__ in,
                                       __half* __restrict__ out, int ngroups)
{
    int g = blockIdx.x * blockDim.x + threadIdx.x;
    if (g >= ngroups) return;
    const float* src = in + (size_t)g * 16;
    float f[16];
    #pragma unroll
    for (int i = 0; i < 16; i += 4)
        *(float4*)&f[i] = *(const float4*)(src + i);
    uint32_t u[8];
    #pragma unroll
    for (int s = 0; s < 8; s++) {
        const int uu = (s >> 1) + (s & 1) * 4;
        u[s] = pack_f16x2(f[2 * uu], f[2 * uu + 1]);
    }
    uint4* dst = (uint4*)(out + (size_t)g * 16);
    dst[0] = make_uint4(u[0], u[1], u[2], u[3]);
    dst[1] = make_uint4(u[4], u[5], u[6], u[7]);
}

// ---------------------------------------------------------------------------
// Weight transpose -> fp16 pair-pack-permuted [N,K] rows
// ---------------------------------------------------------------------------
__global__ void transpose_f16perm_kernel(const float* __restrict__ in,
                                         __half* __restrict__ out, int R, int C_)
{
    __shared__ float tile[32][33];
    const int c0 = blockIdx.x * 32, r0 = blockIdx.y * 32;
    const int tx = threadIdx.x, ty = threadIdx.y;
    #pragma unroll
    for (int i = 0; i < 32; i += 8)
        tile[ty + i][tx] = in[(size_t)(r0 + ty + i) * C_ + c0 + tx];
    __syncthreads();
    const int k = r0 + tx;
    const int pk = (k & ~15) + pp_slot((k >> 1) & 7) * 2 + (k & 1);
    #pragma unroll
    for (int i = 0; i < 32; i += 8)
        out[(size_t)(c0 + ty + i) * R + pk] = __float2half_rn(tile[tx][ty + i]);
}

// ---------------------------------------------------------------------------
// fp16 mma.sync GEMM, BK=64, single-barrier double-buffer.
// qkv_mode=1: epilogue writes transformed Q/K (fp16 perm) and V tensors.
// ---------------------------------------------------------------------------
#define GBM 128
#define GBK 64
#define GPIT 20                       // u64 pitch per row (16 data + 4 pad)
#define GSTG (GBM * GPIT)             // u64 per stage per matrix (2560)
#define GEMM_SMEM (4 * GSTG * 8)      // 81,920 B

__global__ __launch_bounds__(256, 2)
void gemm_f16_kernel(const __half* __restrict__ A, const __half* __restrict__ Bt,
                     const float* __restrict__ bias, float* __restrict__ C,
                     int M, int N, int K, int qkv_mode,
                     uint32_t* __restrict__ Cq, uint32_t* __restrict__ Ck,
                     __half* __restrict__ Cv)
{
    extern __shared__ __align__(16) char gsm_raw[];
    uint2* As64 = (uint2*)gsm_raw;            // stages 0,1
    uint2* Bs64 = As64 + 2 * GSTG;            // stages 0,1

    const int tid  = threadIdx.x;
    const int wid  = tid >> 5;
    const int lane = tid & 31;
    const int gid  = lane >> 2;
    const int tig  = lane & 3;

    const int warp_m = wid & 1;
    const int warp_n = wid >> 1;

    const int brow = blockIdx.y, bcol = blockIdx.x;
    const __half* Abase = A  + (size_t)brow * GBM * K;
    const __half* Bbase = Bt + (size_t)bcol * GBM * K;

    float acc[4][4][4];
    #pragma unroll
    for (int i = 0; i < 4; i++)
        #pragma unroll
        for (int j = 0; j < 4; j++)
            #pragma unroll
            for (int r = 0; r < 4; r++) acc[i][j][r] = 0.0f;

    auto load_tile = [&](int it, int stage) {
        const int koff = it * GBK;
        #pragma unroll
        for (int q = 0; q < 4; q++) {
            const int idx = q * 256 + tid;   // 0..1023
            const int row = idx >> 3;        // 0..127
            const int c8  = idx & 7;
            const int ds  = stage * GSTG + row * GPIT + c8 * 2;
            cp_async16(smem_u32(As64 + ds),
                       Abase + (size_t)row * K + koff + c8 * 8);
            cp_async16(smem_u32(Bs64 + ds),
                       Bbase + (size_t)row * K + koff + c8 * 8);
        }
    };

    const int nit = K / GBK;
    load_tile(0, 0);
    cp_commit();

    for (int it = 0; it < nit; ++it) {
        cp_wait0();
        __syncthreads();   // data(it) visible to all; compute(it-1) done by all
        if (it + 1 < nit) {
            load_tile(it + 1, (it + 1) & 1);   // safe: overwrites stage(it-1)
            cp_commit();
        }

        const uint2* As_ = As64 + (it & 1) * GSTG;
        const uint2* Bs_ = Bs64 + (it & 1) * GSTG;
        #pragma unroll
        for (int kk = 0; kk < 4; kk++) {
            uint32_t a[4][4];
            uint32_t b[4][2];
            #pragma unroll
            for (int i = 0; i < 4; i++) {
                const int r = warp_m * 64 + i * 16 + gid;
                const uint2 a02 = As_[r * GPIT + kk * 4 + tig];
                const uint2 a13 = As_[(r + 8) * GPIT + kk * 4 + tig];
                a[i][0] = a02.x; a[i][1] = a13.x;
                a[i][2] = a02.y; a[i][3] = a13.y;
            }
            #pragma unroll
            for (int j = 0; j < 4; j++) {
                const int rn = warp_n * 32 + j * 8 + gid;
                const uint2 bb = Bs_[rn * GPIT + kk * 4 + tig];
                b[j][0] = bb.x; b[j][1] = bb.y;
            }
            #pragma unroll
            for (int i = 0; i < 4; i++)
                #pragma unroll
                for (int j = 0; j < 4; j++)
                    mma_f16(acc[i][j], a[i], b[j][0], b[j][1]);
        }
    }

    if (!qkv_mode) {
        #pragma unroll
        for (int i = 0; i < 4; i++) {
            const int row0 = brow * GBM + warp_m * 64 + i * 16 + gid;
            #pragma unroll
            for (int j = 0; j < 4; j++) {
                const int col = bcol * GBM + warp_n * 32 + j * 8 + 2 * tig;
                const float bx = bias[col], by = bias[col + 1];
                float2 v0 = make_float2(acc[i][j][0] + bx, acc[i][j][1] + by);
                float2 v1 = make_float2(acc[i][j][2] + bx, acc[i][j][3] + by);
                *(float2*)(C + (size_t)row0 * N + col) = v0;
                *(float2*)(C + (size_t)(row0 + 8) * N + col) = v1;
            }
        }
        return;
    }

    // qkv mode: section uniform per CTA (8 bcol blocks per 1024-col section)
    const int sec = bcol >> 3;
    #pragma unroll
    for (int i = 0; i < 4; i++) {
        const int t0 = brow * GBM + warp_m * 64 + i * 16 + gid;
        #pragma unroll
        for (int j = 0; j < 4; j++) {
            const int c = bcol * GBM + warp_n * 32 + j * 8 + 2 * tig;
            const float bx = bias[c], by = bias[c + 1];
            const float a0 = acc[i][j][0] + bx, a1 = acc[i][j][1] + by;
            const float a2 = acc[i][j][2] + bx, a3 = acc[i][j][3] + by;
            const int cc = c & (CC - 1);
            const int h = cc >> 6, d = cc & 63;
            const int u = d >> 1;   // 0..31
            const int slot = ((u >> 3) << 3) + ((u & 3) << 1) + ((u & 7) >> 2);

            if (sec == 0) {
                // Q: fp16 pair-packed, prescaled into exp2 domain
                const size_t r0o = (size_t)t0 * (CC / 2) + h * 32 + slot;
                const size_t r1o = (size_t)(t0 + 8) * (CC / 2) + h * 32 + slot;
                Cq[r0o] = pack_f16x2(a0 * SCALE_EXP2, a1 * SCALE_EXP2);
                Cq[r1o] = pack_f16x2(a2 * SCALE_EXP2, a3 * SCALE_EXP2);
            } else if (sec == 1) {
                // K: fp16 pair-packed
                const size_t r0o = (size_t)t0 * (CC / 2) + h * 32 + slot;
                const size_t r1o = (size_t)(t0 + 8) * (CC / 2) + h * 32 + slot;
                Ck[r0o] = pack_f16x2(a0, a1);
                Ck[r1o] = pack_f16x2(a2, a3);
            } else {
                // V: fp16, [b,tile,h][d][tk_perm]
                #pragma unroll
                for (int rr = 0; rr < 2; rr++) {
                    const int t = t0 + rr * 8;
                    const int b_ = t >> 11, tl = t & (TT - 1);
                    const int tile = tl >> 6, tk = tl & 63;
                    const int wv = tk >> 1, hf = tk & 1;
                    const int vs = ((wv >> 3) << 3) + ((wv & 3) << 1) + ((wv & 7) >> 2);
                    const int pos = 2 * vs + hf;
                    __half* vb = Cv + ((((size_t)b_ * (TT / 64) + tile) * HH + h) << 12);
                    const float va = rr ? a2 : a0;
                    const float vc = rr ? a3 : a1;
                    vb[d * 64 + pos]       = __float2half_rn(va);
                    vb[(d + 1) * 64 + pos] = __float2half_rn(vc);
                }
            }
        }
    }
}

// ---------------------------------------------------------------------------
// Flash attention: plain fp16 S + fp16 k16 PV, f16x2 approx-exp softmax,
// single-barrier double-buffered tiles.
// smem (u64 units): stage = K 64x20 + VT 64x20 = 2560; Q = 128x20 = 2560.
// ---------------------------------------------------------------------------
#define KP64 20
#define STAGE_U64 (2 * 64 * KP64)         // 2560 u64 = 20,480 B
#define ATTN_SMEM ((2 * STAGE_U64 + 128 * KP64) * 8)   // 61,440 B

__global__ __launch_bounds__(256, 2)
void attn_hyb_kernel(const uint32_t* __restrict__ gq,
                     const uint32_t* __restrict__ gk,
                     const __half* __restrict__ gv,
                     __half* __restrict__ out)
{
    extern __shared__ __align__(16) char asm_raw[];
    uint2* smu  = (uint2*)asm_raw;
    uint2* qbuf = smu + 2 * STAGE_U64;

    const int qb = (int)gridDim.x - 1 - (int)blockIdx.x;
    const int h  = blockIdx.y;
    const int b  = blockIdx.z;
    const int q0 = qb * 128;
    const size_t bT = (size_t)b * TT;

    const int tid  = threadIdx.x;
    const int w    = tid >> 5;
    const int lane = tid & 31;
    const int gid  = lane >> 2;
    const int tig  = lane & 3;

    const int ntiles = 2 * (qb + 1);

    // Tile loader: pure cp.async, 4 x 16B per thread
    auto load_tile = [&](int t, int stage) {
        uint2* base = smu + (size_t)stage * STAGE_U64;
        const size_t kro = (bT + (size_t)t * 64) * (CC / 2) + h * 32;
        const __half* vb = gv + ((((size_t)b * (TT / 64) + t) * HH + h) << 12);
        #pragma unroll
        for (int q = 0; q < 2; q++) {
            const int idx = q * 256 + tid;       // 0..511
            const int row = idx >> 3;            // 0..63
            const int c8  = idx & 7;
            cp_async16(smem_u32(base + row * KP64 + c8 * 2),
                       gk + kro + (size_t)row * (CC / 2) + c8 * 4);
            cp_async16(smem_u32(base + 64 * KP64 + row * KP64 + c8 * 2),
                       vb + row * 64 + c8 * 8);
        }
    };

    // Prologue: Q copy (group 0), tile-0 prefetch (group 1)
    {
        const size_t qro = (bT + q0) * (CC / 2) + h * 32;
        #pragma unroll
        for (int q = 0; q < 4; q++) {
            const int idx = q * 256 + tid;       // 0..1023
            const int row = idx >> 3;            // 0..127
            const int c8  = idx & 7;             // 8 x 16B per 128B row
            cp_async16(smem_u32(qbuf + row * KP64 + c8 * 2),
                       gq + qro + (size_t)row * (CC / 2) + c8 * 4);
        }
    }
    cp_commit();
    load_tile(0, 0);
    cp_commit();

    cp_wait1();          // Q done (tile 0 may still be in flight)
    __syncthreads();

    // Extract Q fp16 A-fragments (already prescaled + permuted)
    const int r0l = w * 16 + gid;
    const int r0g = q0 + r0l;
    uint32_t qf[4][4];
    #pragma unroll
    for (int ks = 0; ks < 4; ks++) {
        const uint2 a02 = qbuf[r0l * KP64 + ks * 4 + tig];
        const uint2 a13 = qbuf[(r0l + 8) * KP64 + ks * 4 + tig];
        qf[ks][0] = a02.x; qf[ks][1] = a13.x;
        qf[ks][2] = a02.y; qf[ks][3] = a13.y;
    }

    float O[8][4];
    #pragma unroll
    for (int j = 0; j < 8; j++)
        #pragma unroll
        for (int r = 0; r < 4; r++) O[j][r] = 0.0f;
    float m0 = -1e30f, m1 = -1e30f, l0 = 0.0f, l1 = 0.0f;

    for (int t = 0; t < ntiles; t++) {
        cp_wait0();
        __syncthreads();   // tile(t) visible; compute(t-1) done by all warps
        if (t + 1 < ntiles) {
            load_tile(t + 1, (t + 1) & 1);
            cp_commit();
        }

        const uint2* KK2 = smu + (size_t)(t & 1) * STAGE_U64;
        const uint2* VT2 = KK2 + 64 * KP64;
        const int kv0 = t * 64;

        // S = Q @ K^T (plain fp16)
        float s[8][4];
        #pragma unroll
        for (int j = 0; j < 8; j++)
            #pragma unroll
            for (int r = 0; r < 4; r++) s[j][r] = 0.0f;

        #pragma unroll
        for (int ks = 0; ks < 4; ks++) {
            #pragma unroll
            for (int j = 0; j < 8; j++) {
                const uint2 bh = KK2[(j * 8 + gid) * KP64 + ks * 4 + tig];
                mma_f16(s[j], qf[ks], bh.x, bh.y);
            }
        }

        // Causal mask on the two diagonal-straddling tiles
        if (t + 2 >= ntiles) {
            #pragma unroll
            for (int j = 0; j < 8; j++) {
                const int col = kv0 + j * 8 + 2 * tig;
                if (col     > r0g)     s[j][0] = -1e30f;
                if (col + 1 > r0g)     s[j][1] = -1e30f;
                if (col     > r0g + 8) s[j][2] = -1e30f;
                if (col + 1 > r0g + 8) s[j][3] = -1e30f;
            }
        }

        // Online softmax (exp2 domain)
        float mt0 = s[0][0], mt1 = s[0][2];
        #pragma unroll
        for (int j = 0; j < 8; j++) {
            mt0 = fmaxf(mt0, fmaxf(s[j][0], s[j][1]));
            mt1 = fmaxf(mt1, fmaxf(s[j][2], s[j][3]));
        }
        mt0 = fmaxf(mt0, __shfl_xor_sync(0xffffffffu, mt0, 1));
        mt0 = fmaxf(mt0, __shfl_xor_sync(0xffffffffu, mt0, 2));
        mt1 = fmaxf(mt1, __shfl_xor_sync(0xffffffffu, mt1, 1));
        mt1 = fmaxf(mt1, __shfl_xor_sync(0xffffffffu, mt1, 2));

        const float mn0 = fmaxf(m0, mt0), mn1 = fmaxf(m1, mt1);
        const float c0 = ex2(m0 - mn0), c1 = ex2(m1 - mn1);
        l0 *= c0; l1 *= c1;
        #pragma unroll
        for (int j = 0; j < 8; j++) {
            O[j][0] *= c0; O[j][1] *= c0;
            O[j][2] *= c1; O[j][3] *= c1;
        }
        m0 = mn0; m1 = mn1;

        // p = exp2(s - m) computed in f16x2 (feeds PV A-fragments directly)
        uint32_t P01[8], P23[8];
        #pragma unroll
        for (int j = 0; j < 8; j++) {
            uint32_t p01 = pack_f16x2(s[j][0] - mn0, s[j][1] - mn0);
            uint32_t p23 = pack_f16x2(s[j][2] - mn1, s[j][3] - mn1);
            p01 = ex2_f16x2(p01);
            p23 = ex2_f16x2(p23);
            P01[j] = p01; P23[j] = p23;
            const float2 f01 = __half22float2(*(__half2*)&p01);
            const float2 f23 = __half22float2(*(__half2*)&p23);
            l0 += f01.x + f01.y;
            l1 += f23.x + f23.y;
        }

        // PV: fp16 k16
        #pragma unroll
        for (int jk = 0; jk < 4; jk++) {
            uint32_t a[4];
            a[0] = P01[2 * jk];
            a[1] = P23[2 * jk];
            a[2] = P01[2 * jk + 1];
            a[3] = P23[2 * jk + 1];
            #pragma unroll
            for (int jo = 0; jo < 8; jo++) {
                const uint2 vv = VT2[(jo * 8 + gid) * KP64 + jk * 4 + tig];
                mma_f16(O[jo], a, vv.x, vv.y);
            }
        }
    }

    // Finalize: write fp16 pair-pack-permuted rows into g_att16
    l0 += __shfl_xor_sync(0xffffffffu, l0, 1);
    l0 += __shfl_xor_sync(0xffffffffu, l0, 2);
    l1 += __shfl_xor_sync(0xffffffffu, l1, 1);
    l1 += __shfl_xor_sync(0xffffffffu, l1, 2);
    const float i0 = 1.0f / l0, i1 = 1.0f / l1;

    __half* ob = out + (bT + r0g) * CC + h * DD;
    #pragma unroll
    for (int j = 0; j < 8; j++) {
        const int off = ((j >> 1) << 4) + ((2 * tig + (j & 1)) << 1);
        *(uint32_t*)(ob + off) =
            pack_f16x2(O[j][0] * i0, O[j][1] * i0);
        *(uint32_t*)(ob + (size_t)8 * CC + off) =
            pack_f16x2(O[j][2] * i1, O[j][3] * i1);
    }
}

// ---------------------------------------------------------------------------
// Launch
// ---------------------------------------------------------------------------
extern "C" void kernel_launch(void* const* d_in, const int* in_sizes, int n_in,
                              void* d_out, int out_size)
{
    const float* x     = (const float*)d_in[0];
    const float* w_qkv = (const float*)d_in[1];
    const float* b_qkv = (const float*)d_in[2];
    const float* w_out = (const float*)d_in[3];
    const float* b_out = (const float*)d_in[4];
    float* out = (float*)d_out;

    uint32_t* gq = nullptr;    cudaGetSymbolAddress((void**)&gq, g_q16);
    uint32_t* gk = nullptr;    cudaGetSymbolAddress((void**)&gk, g_k16);
    __half*   gv = nullptr;    cudaGetSymbolAddress((void**)&gv, g_v16);
    __half*   att16 = nullptr; cudaGetSymbolAddress((void**)&att16, g_att16);
    __half*   x16 = nullptr;   cudaGetSymbolAddress((void**)&x16, g_x16);
    __half*   wqkvT = nullptr; cudaGetSymbolAddress((void**)&wqkvT, g_wqkvT16);
    __half*   woutT = nullptr; cudaGetSymbolAddress((void**)&woutT, g_woutT16);

    cudaFuncSetAttribute(gemm_f16_kernel,
                         cudaFuncAttributeMaxDynamicSharedMemorySize, GEMM_SMEM);
    cudaFuncSetAttribute(attn_hyb_kernel,
                         cudaFuncAttributeMaxDynamicSharedMemorySize, ATTN_SMEM);

    // Preproc: x -> fp16 perm; weights -> transposed fp16 perm
    {
        const int ngroups = MM * CC / 16;
        f16perm_convert_kernel<<<ngroups / 256, 256>>>(x, x16, ngroups);
        dim3 blk(32, 8);
        transpose_f16perm_kernel<<<dim3((3 * CC) / 32, CC / 32), blk>>>(w_qkv, wqkvT, CC, 3 * CC);
        transpose_f16perm_kernel<<<dim3(CC / 32, CC / 32), blk>>>(w_out, woutT, CC, CC);
    }

    // QKV projection (fp16 mma, BK=64) with fused Q/K/V transformation
    {
        dim3 grid((3 * CC) / 128, MM / 128);
        gemm_f16_kernel<<<grid, 256, GEMM_SMEM>>>(x16, wqkvT, b_qkv, nullptr,
                                                  MM, 3 * CC, CC, 1,
                                                  gq, gk, gv);
    }

    // Flash attention (plain fp16 S / fp16 PV, f16x2 exp softmax)
    {
        dim3 grid(TT / 128, HH, BB);
        attn_hyb_kernel<<<grid, 256, ATTN_SMEM>>>(gq, gk, gv, att16);
    }

    // Output projection (fp16 mma, BK=64, plain epilogue)
    {
        dim3 grid(CC / 128, MM / 128);
        gemm_f16_kernel<<<grid, 256, GEMM_SMEM>>>(att16, woutT, b_out, out,
                                                  MM, CC, CC, 0,
                                                  nullptr, nullptr, nullptr);
    }
}

// round 16
// speedup vs baseline: 1.1112x; 1.1112x over previous
#include <cuda_runtime.h>
#include <cuda_bf16.h>
#include <cuda_fp16.h>
#include <cstdint>

// Problem constants
#define BB 4
#define TT 2048
#define CC 1024
#define HH 16
#define DD 64
#define MM (BB*TT)        // 8192

#define SCALE_EXP2 0.1803368801111204f   // 0.125 * log2(e)

// Scratch (device globals: allocation-free rule)
__device__ uint32_t g_q16[(size_t)MM * CC / 2];  // fp16 pair-packed prescaled Q
__device__ uint32_t g_k16[(size_t)MM * CC / 2];  // fp16 pair-packed K
__device__ __half   g_v16[(size_t)MM * CC];      // fp16 V, [b,tile,h][d][tk_perm]
__device__ __half   g_att16[(size_t)MM * CC];    // attention out, fp16 natural
__device__ __half   g_x16[(size_t)MM * CC];      // fp16 natural x
__device__ __half   g_wqkvT16[(size_t)3 * CC * CC];  // natural [N][K]
__device__ __half   g_woutT16[(size_t)CC * CC];      // natural [N][K]

// ---------------------------------------------------------------------------
// Helpers
// ---------------------------------------------------------------------------
__device__ __forceinline__ float ex2(float x) {
    float y;
    asm("ex2.approx.ftz.f32 %0, %1;" : "=f"(y) : "f"(x));
    return y;
}

__device__ __forceinline__ uint32_t pack_f16x2(float x, float y) {
    uint32_t r;
    asm("cvt.rn.f16x2.f32 %0, %1, %2;" : "=r"(r) : "f"(y), "f"(x));
    return r;
}

// m16n8k16 f16 mma, fp32 accumulate
__device__ __forceinline__ void mma_f16(float* c, const uint32_t* a,
                                        uint32_t b0, uint32_t b1) {
    asm volatile(
        "mma.sync.aligned.m16n8k16.row.col.f32.f16.f16.f32 "
        "{%0,%1,%2,%3}, {%4,%5,%6,%7}, {%8,%9}, {%0,%1,%2,%3};\n"
        : "+f"(c[0]), "+f"(c[1]), "+f"(c[2]), "+f"(c[3])
        : "r"(a[0]), "r"(a[1]), "r"(a[2]), "r"(a[3]),
          "r"(b0), "r"(b1));
}

// ldmatrix: 4 x (8x8 b16) matrices
__device__ __forceinline__ void ldsm_x4(uint32_t* r, uint32_t addr) {
    asm volatile("ldmatrix.sync.aligned.m8n8.x4.shared.b16 {%0,%1,%2,%3}, [%4];"
        : "=r"(r[0]), "=r"(r[1]), "=r"(r[2]), "=r"(r[3]) : "r"(addr));
}

__device__ __forceinline__ void cp_async16(uint32_t dst, const void* src) {
    asm volatile("cp.async.cg.shared.global [%0], [%1], 16;\n"
                 :: "r"(dst), "l"(src));
}
__device__ __forceinline__ void cp_commit() {
    asm volatile("cp.async.commit_group;\n" ::: "memory");
}
__device__ __forceinline__ void cp_wait1() {
    asm volatile("cp.async.wait_group 1;\n" ::: "memory");
}
__device__ __forceinline__ void cp_wait0() {
    asm volatile("cp.async.wait_group 0;\n" ::: "memory");
}

__device__ __forceinline__ uint32_t smem_u32(const void* p) {
    uint32_t a;
    asm("{ .reg .u64 t; cvta.to.shared.u64 t, %1; cvt.u32.u64 %0, t; }"
        : "=r"(a) : "l"(p));
    return a;
}

// ---------------------------------------------------------------------------
// x -> fp16 natural (GEMM A operand; ldmatrix handles fragment layout)
// ---------------------------------------------------------------------------
__global__ void f16_convert_kernel(const float* __restrict__ in,
                                   __half* __restrict__ out, int n)
{
    int i = (blockIdx.x * blockDim.x + threadIdx.x) * 8;
    if (i < n) {
        float4 v0 = *(const float4*)(in + i);
        float4 v1 = *(const float4*)(in + i + 4);
        uint4 o;
        o.x = pack_f16x2(v0.x, v0.y);
        o.y = pack_f16x2(v0.z, v0.w);
        o.z = pack_f16x2(v1.x, v1.y);
        o.w = pack_f16x2(v1.z, v1.w);
        *(uint4*)(out + i) = o;
    }
}

// ---------------------------------------------------------------------------
// Weight transpose -> fp16 natural [N][K]
// ---------------------------------------------------------------------------
__global__ void transpose_f16_kernel(const float* __restrict__ in,
                                     __half* __restrict__ out, int R, int C_)
{
    __shared__ float tile[32][33];
    const int c0 = blockIdx.x * 32, r0 = blockIdx.y * 32;
    const int tx = threadIdx.x, ty = threadIdx.y;
    #pragma unroll
    for (int i = 0; i < 32; i += 8)
        tile[ty + i][tx] = in[(size_t)(r0 + ty + i) * C_ + c0 + tx];
    __syncthreads();
    #pragma unroll
    for (int i = 0; i < 32; i += 8)
        out[(size_t)(c0 + ty + i) * R + r0 + tx] = __float2half_rn(tile[tx][ty + i]);
}

// ---------------------------------------------------------------------------
// fp16 mma.sync GEMM, BK=64, ldmatrix operand delivery.
// smem: natural fp16 rows, 128 B/row, 16B chunks XOR-swizzled by (row&7).
// As: stage s at s*16KB; Bs at 32KB + s*16KB. Total 64 KB dynamic.
// qkv_mode=1: epilogue writes transformed Q/K (fp16 perm) and V tensors.
// ---------------------------------------------------------------------------
#define GBM 128
#define GBK 64
#define GEMM_SMEM 65536

__global__ __launch_bounds__(256, 2)
void gemm_f16_kernel(const __half* __restrict__ A, const __half* __restrict__ Bt,
                     const float* __restrict__ bias, float* __restrict__ C,
                     int M, int N, int K, int qkv_mode,
                     uint32_t* __restrict__ Cq, uint32_t* __restrict__ Ck,
                     __half* __restrict__ Cv)
{
    extern __shared__ __align__(16) char gsm_raw[];
    const uint32_t sA = smem_u32(gsm_raw);
    const uint32_t sB = sA + 32768;

    const int tid  = threadIdx.x;
    const int wid  = tid >> 5;
    const int lane = tid & 31;
    const int gid  = lane >> 2;
    const int tig  = lane & 3;

    const int warp_m = wid & 1;
    const int warp_n = wid >> 1;

    const int brow = blockIdx.y, bcol = blockIdx.x;
    const __half* Abase = A  + (size_t)brow * GBM * K;
    const __half* Bbase = Bt + (size_t)bcol * GBM * K;

    float acc[4][4][4];
    #pragma unroll
    for (int i = 0; i < 4; i++)
        #pragma unroll
        for (int j = 0; j < 4; j++)
            #pragma unroll
            for (int r = 0; r < 4; r++) acc[i][j][r] = 0.0f;

    // ldmatrix per-thread address components
    const int x7   = lane & 7;
    const int msel = lane >> 3;                    // matrix select 0..3
    const uint32_t aRowOff = (uint32_t)(warp_m * 64 + (msel & 1) * 8 + x7) * 128;
    const uint32_t bRowOff = (uint32_t)(warp_n * 32 + x7) * 128;
    uint32_t akoff[4], bkoff[2];
    #pragma unroll
    for (int kk = 0; kk < 4; kk++)
        akoff[kk] = (uint32_t)(((2 * kk + (msel >> 1)) ^ x7) << 4);
    #pragma unroll
    for (int p = 0; p < 2; p++)
        bkoff[p] = (uint32_t)(((4 * p + msel) ^ x7) << 4);

    auto load_tile = [&](int it, int stage) {
        const int koff = it * GBK;
        const uint32_t aS = sA + stage * 16384;
        const uint32_t bS = sB + stage * 16384;
        #pragma unroll
        for (int q = 0; q < 4; q++) {
            const int idx = q * 256 + tid;   // 0..1023
            const int row = idx >> 3;        // 0..127
            const int c8  = idx & 7;
            const uint32_t doff = (uint32_t)row * 128
                                + (uint32_t)((c8 ^ (row & 7)) << 4);
            cp_async16(aS + doff, Abase + (size_t)row * K + koff + c8 * 8);
            cp_async16(bS + doff, Bbase + (size_t)row * K + koff + c8 * 8);
        }
    };

    const int nit = K / GBK;
    load_tile(0, 0);
    cp_commit();

    for (int it = 0; it < nit; ++it) {
        if (it + 1 < nit) {
            load_tile(it + 1, (it + 1) & 1);
            cp_commit();
            cp_wait1();
        } else {
            cp_wait0();
        }
        __syncthreads();

        const uint32_t aS = sA + (it & 1) * 16384 + aRowOff;
        const uint32_t bS = sB + (it & 1) * 16384 + bRowOff;

        #pragma unroll
        for (int p = 0; p < 2; p++) {
            uint32_t bf[4][4];
            #pragma unroll
            for (int j = 0; j < 4; j++)
                ldsm_x4(bf[j], bS + (uint32_t)(j << 10) + bkoff[p]);
            #pragma unroll
            for (int kk2 = 0; kk2 < 2; kk2++) {
                const int kk = 2 * p + kk2;
                uint32_t af[4][4];
                #pragma unroll
                for (int i = 0; i < 4; i++)
                    ldsm_x4(af[i], aS + (uint32_t)(i << 11) + akoff[kk]);
                #pragma unroll
                for (int i = 0; i < 4; i++)
                    #pragma unroll
                    for (int j = 0; j < 4; j++)
                        mma_f16(acc[i][j], af[i], bf[j][2 * kk2], bf[j][2 * kk2 + 1]);
            }
        }
        __syncthreads();
    }

    if (!qkv_mode) {
        #pragma unroll
        for (int i = 0; i < 4; i++) {
            const int row0 = brow * GBM + warp_m * 64 + i * 16 + gid;
            #pragma unroll
            for (int j = 0; j < 4; j++) {
                const int col = bcol * GBM + warp_n * 32 + j * 8 + 2 * tig;
                const float bx = bias[col], by = bias[col + 1];
                float2 v0 = make_float2(acc[i][j][0] + bx, acc[i][j][1] + by);
                float2 v1 = make_float2(acc[i][j][2] + bx, acc[i][j][3] + by);
                *(float2*)(C + (size_t)row0 * N + col) = v0;
                *(float2*)(C + (size_t)(row0 + 8) * N + col) = v1;
            }
        }
        return;
    }

    // qkv mode: section uniform per CTA (8 bcol blocks per 1024-col section)
    const int sec = bcol >> 3;
    #pragma unroll
    for (int i = 0; i < 4; i++) {
        const int t0 = brow * GBM + warp_m * 64 + i * 16 + gid;
        #pragma unroll
        for (int j = 0; j < 4; j++) {
            const int c = bcol * GBM + warp_n * 32 + j * 8 + 2 * tig;
            const float bx = bias[c], by = bias[c + 1];
            const float a0 = acc[i][j][0] + bx, a1 = acc[i][j][1] + by;
            const float a2 = acc[i][j][2] + bx, a3 = acc[i][j][3] + by;
            const int cc = c & (CC - 1);
            const int h = cc >> 6, d = cc & 63;
            const int u = d >> 1;   // 0..31
            const int slot = ((u >> 3) << 3) + ((u & 3) << 1) + ((u & 7) >> 2);

            if (sec == 0) {
                // Q: fp16 pair-packed, prescaled into exp2 domain
                const size_t r0o = (size_t)t0 * (CC / 2) + h * 32 + slot;
                const size_t r1o = (size_t)(t0 + 8) * (CC / 2) + h * 32 + slot;
                Cq[r0o] = pack_f16x2(a0 * SCALE_EXP2, a1 * SCALE_EXP2);
                Cq[r1o] = pack_f16x2(a2 * SCALE_EXP2, a3 * SCALE_EXP2);
            } else if (sec == 1) {
                // K: fp16 pair-packed
                const size_t r0o = (size_t)t0 * (CC / 2) + h * 32 + slot;
                const size_t r1o = (size_t)(t0 + 8) * (CC / 2) + h * 32 + slot;
                Ck[r0o] = pack_f16x2(a0, a1);
                Ck[r1o] = pack_f16x2(a2, a3);
            } else {
                // V: fp16, [b,tile,h][d][tk_perm]
                #pragma unroll
                for (int rr = 0; rr < 2; rr++) {
                    const int t = t0 + rr * 8;
                    const int b_ = t >> 11, tl = t & (TT - 1);
                    const int tile = tl >> 6, tk = tl & 63;
                    const int wv = tk >> 1, hf = tk & 1;
                    const int vs = ((wv >> 3) << 3) + ((wv & 3) << 1) + ((wv & 7) >> 2);
                    const int pos = 2 * vs + hf;
                    __half* vb = Cv + ((((size_t)b_ * (TT / 64) + tile) * HH + h) << 12);
                    const float va = rr ? a2 : a0;
                    const float vc = rr ? a3 : a1;
                    vb[d * 64 + pos]       = __float2half_rn(va);
                    vb[(d + 1) * 64 + pos] = __float2half_rn(vc);
                }
            }
        }
    }
}

// ---------------------------------------------------------------------------
// Flash attention: plain fp16 S + fp16 k16 PV (round-14 version, 373.5us).
// Only change: epilogue writes NATURAL fp16 rows (out-proj uses ldmatrix now).
// smem (u64 units): stage = K 64x20 + VT 64x20 = 2560; Q = 128x20 = 2560.
// ---------------------------------------------------------------------------
#define KP64 20
#define STAGE_U64 (2 * 64 * KP64)         // 2560 u64 = 20,480 B
#define ATTN_SMEM ((2 * STAGE_U64 + 128 * KP64) * 8)   // 61,440 B

__global__ __launch_bounds__(256, 2)
void attn_hyb_kernel(const uint32_t* __restrict__ gq,
                     const uint32_t* __restrict__ gk,
                     const __half* __restrict__ gv,
                     __half* __restrict__ out)
{
    extern __shared__ __align__(16) char asm_raw[];
    uint2* smu  = (uint2*)asm_raw;
    uint2* qbuf = smu + 2 * STAGE_U64;

    const int qb = (int)gridDim.x - 1 - (int)blockIdx.x;
    const int h  = blockIdx.y;
    const int b  = blockIdx.z;
    const int q0 = qb * 128;
    const size_t bT = (size_t)b * TT;

    const int tid  = threadIdx.x;
    const int w    = tid >> 5;
    const int lane = tid & 31;
    const int gid  = lane >> 2;
    const int tig  = lane & 3;

    const int ntiles = 2 * (qb + 1);

    auto load_tile = [&](int t, int stage) {
        uint2* base = smu + (size_t)stage * STAGE_U64;
        const size_t kro = (bT + (size_t)t * 64) * (CC / 2) + h * 32;
        const __half* vb = gv + ((((size_t)b * (TT / 64) + t) * HH + h) << 12);
        #pragma unroll
        for (int q = 0; q < 2; q++) {
            const int idx = q * 256 + tid;       // 0..511
            const int row = idx >> 3;            // 0..63
            const int c8  = idx & 7;
            cp_async16(smem_u32(base + row * KP64 + c8 * 2),
                       gk + kro + (size_t)row * (CC / 2) + c8 * 4);
            cp_async16(smem_u32(base + 64 * KP64 + row * KP64 + c8 * 2),
                       vb + row * 64 + c8 * 8);
        }
    };

    // Prologue: Q copy (group 0), tile-0 prefetch (group 1)
    {
        const size_t qro = (bT + q0) * (CC / 2) + h * 32;
        #pragma unroll
        for (int q = 0; q < 4; q++) {
            const int idx = q * 256 + tid;       // 0..1023
            const int row = idx >> 3;            // 0..127
            const int c8  = idx & 7;
            cp_async16(smem_u32(qbuf + row * KP64 + c8 * 2),
                       gq + qro + (size_t)row * (CC / 2) + c8 * 4);
        }
    }
    cp_commit();
    load_tile(0, 0);
    cp_commit();

    cp_wait1();
    __syncthreads();

    const int r0l = w * 16 + gid;
    const int r0g = q0 + r0l;
    uint32_t qf[4][4];
    #pragma unroll
    for (int ks = 0; ks < 4; ks++) {
        const uint2 a02 = qbuf[r0l * KP64 + ks * 4 + tig];
        const uint2 a13 = qbuf[(r0l + 8) * KP64 + ks * 4 + tig];
        qf[ks][0] = a02.x; qf[ks][1] = a13.x;
        qf[ks][2] = a02.y; qf[ks][3] = a13.y;
    }

    float O[8][4];
    #pragma unroll
    for (int j = 0; j < 8; j++)
        #pragma unroll
        for (int r = 0; r < 4; r++) O[j][r] = 0.0f;
    float m0 = -1e30f, m1 = -1e30f, l0 = 0.0f, l1 = 0.0f;

    for (int t = 0; t < ntiles; t++) {
        if (t + 1 < ntiles) {
            load_tile(t + 1, (t + 1) & 1);
            cp_commit();
            cp_wait1();
        } else {
            cp_wait0();
        }
        __syncthreads();

        const uint2* KK2 = smu + (size_t)(t & 1) * STAGE_U64;
        const uint2* VT2 = KK2 + 64 * KP64;
        const int kv0 = t * 64;

        float s[8][4];
        #pragma unroll
        for (int j = 0; j < 8; j++)
            #pragma unroll
            for (int r = 0; r < 4; r++) s[j][r] = 0.0f;

        #pragma unroll
        for (int ks = 0; ks < 4; ks++) {
            #pragma unroll
            for (int j = 0; j < 8; j++) {
                const uint2 bh = KK2[(j * 8 + gid) * KP64 + ks * 4 + tig];
                mma_f16(s[j], qf[ks], bh.x, bh.y);
            }
        }

        if (t + 2 >= ntiles) {
            #pragma unroll
            for (int j = 0; j < 8; j++) {
                const int col = kv0 + j * 8 + 2 * tig;
                if (col     > r0g)     s[j][0] = -1e30f;
                if (col + 1 > r0g)     s[j][1] = -1e30f;
                if (col     > r0g + 8) s[j][2] = -1e30f;
                if (col + 1 > r0g + 8) s[j][3] = -1e30f;
            }
        }

        float mt0 = s[0][0], mt1 = s[0][2];
        #pragma unroll
        for (int j = 0; j < 8; j++) {
            mt0 = fmaxf(mt0, fmaxf(s[j][0], s[j][1]));
            mt1 = fmaxf(mt1, fmaxf(s[j][2], s[j][3]));
        }
        mt0 = fmaxf(mt0, __shfl_xor_sync(0xffffffffu, mt0, 1));
        mt0 = fmaxf(mt0, __shfl_xor_sync(0xffffffffu, mt0, 2));
        mt1 = fmaxf(mt1, __shfl_xor_sync(0xffffffffu, mt1, 1));
        mt1 = fmaxf(mt1, __shfl_xor_sync(0xffffffffu, mt1, 2));

        const float mn0 = fmaxf(m0, mt0), mn1 = fmaxf(m1, mt1);
        const float c0 = ex2(m0 - mn0), c1 = ex2(m1 - mn1);
        l0 *= c0; l1 *= c1;
        #pragma unroll
        for (int j = 0; j < 8; j++) {
            O[j][0] *= c0; O[j][1] *= c0;
            O[j][2] *= c1; O[j][3] *= c1;
        }
        m0 = mn0; m1 = mn1;

        #pragma unroll
        for (int j = 0; j < 8; j++) {
            s[j][0] = ex2(s[j][0] - mn0);
            s[j][1] = ex2(s[j][1] - mn0);
            s[j][2] = ex2(s[j][2] - mn1);
            s[j][3] = ex2(s[j][3] - mn1);
            l0 += s[j][0] + s[j][1];
            l1 += s[j][2] + s[j][3];
        }

        #pragma unroll
        for (int jk = 0; jk < 4; jk++) {
            uint32_t a[4];
            a[0] = pack_f16x2(s[2 * jk][0],     s[2 * jk][1]);
            a[1] = pack_f16x2(s[2 * jk][2],     s[2 * jk][3]);
            a[2] = pack_f16x2(s[2 * jk + 1][0], s[2 * jk + 1][1]);
            a[3] = pack_f16x2(s[2 * jk + 1][2], s[2 * jk + 1][3]);
            #pragma unroll
            for (int jo = 0; jo < 8; jo++) {
                const uint2 vv = VT2[(jo * 8 + gid) * KP64 + jk * 4 + tig];
                mma_f16(O[jo], a, vv.x, vv.y);
            }
        }
        __syncthreads();
    }

    // Finalize: write NATURAL fp16 rows into g_att16
    l0 += __shfl_xor_sync(0xffffffffu, l0, 1);
    l0 += __shfl_xor_sync(0xffffffffu, l0, 2);
    l1 += __shfl_xor_sync(0xffffffffu, l1, 1);
    l1 += __shfl_xor_sync(0xffffffffu, l1, 2);
    const float i0 = 1.0f / l0, i1 = 1.0f / l1;

    __half* ob = out + (bT + r0g) * CC + h * DD;
    #pragma unroll
    for (int j = 0; j < 8; j++) {
        const int off = j * 8 + 2 * tig;
        *(uint32_t*)(ob + off) =
            pack_f16x2(O[j][0] * i0, O[j][1] * i0);
        *(uint32_t*)(ob + (size_t)8 * CC + off) =
            pack_f16x2(O[j][2] * i1, O[j][3] * i1);
    }
}

// ---------------------------------------------------------------------------
// Launch
// ---------------------------------------------------------------------------
extern "C" void kernel_launch(void* const* d_in, const int* in_sizes, int n_in,
                              void* d_out, int out_size)
{
    const float* x     = (const float*)d_in[0];
    const float* w_qkv = (const float*)d_in[1];
    const float* b_qkv = (const float*)d_in[2];
    const float* w_out = (const float*)d_in[3];
    const float* b_out = (const float*)d_in[4];
    float* out = (float*)d_out;

    uint32_t* gq = nullptr;    cudaGetSymbolAddress((void**)&gq, g_q16);
    uint32_t* gk = nullptr;    cudaGetSymbolAddress((void**)&gk, g_k16);
    __half*   gv = nullptr;    cudaGetSymbolAddress((void**)&gv, g_v16);
    __half*   att16 = nullptr; cudaGetSymbolAddress((void**)&att16, g_att16);
    __half*   x16 = nullptr;   cudaGetSymbolAddress((void**)&x16, g_x16);
    __half*   wqkvT = nullptr; cudaGetSymbolAddress((void**)&wqkvT, g_wqkvT16);
    __half*   woutT = nullptr; cudaGetSymbolAddress((void**)&woutT, g_woutT16);

    cudaFuncSetAttribute(gemm_f16_kernel,
                         cudaFuncAttributeMaxDynamicSharedMemorySize, GEMM_SMEM);
    cudaFuncSetAttribute(attn_hyb_kernel,
                         cudaFuncAttributeMaxDynamicSharedMemorySize, ATTN_SMEM);

    // Preproc: x -> fp16 natural; weights -> transposed fp16 natural
    {
        const int n = MM * CC;
        f16_convert_kernel<<<n / (256 * 8), 256>>>(x, x16, n);
        dim3 blk(32, 8);
        transpose_f16_kernel<<<dim3((3 * CC) / 32, CC / 32), blk>>>(w_qkv, wqkvT, CC, 3 * CC);
        transpose_f16_kernel<<<dim3(CC / 32, CC / 32), blk>>>(w_out, woutT, CC, CC);
    }

    // QKV projection (fp16 mma + ldmatrix) with fused Q/K/V transformation
    {
        dim3 grid((3 * CC) / 128, MM / 128);
        gemm_f16_kernel<<<grid, 256, GEMM_SMEM>>>(x16, wqkvT, b_qkv, nullptr,
                                                  MM, 3 * CC, CC, 1,
                                                  gq, gk, gv);
    }

    // Flash attention (round-14 kernel, natural output)
    {
        dim3 grid(TT / 128, HH, BB);
        attn_hyb_kernel<<<grid, 256, ATTN_SMEM>>>(gq, gk, gv, att16);
    }

    // Output projection (fp16 mma + ldmatrix, plain epilogue)
    {
        dim3 grid(CC / 128, MM / 128);
        gemm_f16_kernel<<<grid, 256, GEMM_SMEM>>>(att16, woutT, b_out, out,
                                                  MM, CC, CC, 0,
                                                  nullptr, nullptr, nullptr);
    }
}